// round 10
// baseline (speedup 1.0000x reference)
#include <cuda_runtime.h>
#include <cuda_bf16.h>
#include <cstdint>
#include <cstddef>

#define NA 120001
#define NB 260001
#define AF 133
#define BF 147
#define HD 256
#define MAXNB 6
#define NMOL 6000
#define APM 20

#define BMT 128           // M rows per CTA
#define BK  32            // K elements per chunk

#define KPAD_I 160
#define KPAD_H 256
#define KPAD_O 416

// SMEM per stage (64B swizzled rows): A 128 rows x2, B 256 rows x2
#define OFF_A_HI 0
#define OFF_A_LO 8192
#define OFF_B_HI 16384
#define OFF_B_LO 32768
#define BUFSZ    49152
#define NSTAGE   3
#define SMEM_TOTAL (NSTAGE * BUFSZ)   // 147456 -> 1 CTA/SM, 16 warps

typedef unsigned int u32;

// ---------------- scratch (device globals; no allocation allowed) ----------
__device__ float g_inp [(size_t)NB * HD];
__device__ float g_msgA[(size_t)NB * HD];
__device__ float g_msgB[(size_t)NB * HD];
__device__ float g_amsg[(size_t)NA * HD];
__device__ float g_hid [(size_t)NA * HD];

// prepacked bf16 hi/lo A-operand images
__device__ __nv_bfloat16 g_Ai[2][(size_t)NB * KPAD_I];  // f_bonds padded
__device__ __nv_bfloat16 g_Ah[2][(size_t)NB * KPAD_H];  // bond-message diff
__device__ __nv_bfloat16 g_Ao[2][(size_t)NA * KPAD_O];  // f_atoms | amsg

// prepacked transposed weights, bf16 hi/lo: [term][N=256][Kpad]
__device__ __nv_bfloat16 g_Bi[2][256 * KPAD_I];
__device__ __nv_bfloat16 g_Bh[2][256 * KPAD_H];
__device__ __nv_bfloat16 g_Bo[2][256 * KPAD_O];

// ---------------- helpers ---------------------------------------------------
__device__ __forceinline__ u32 smem_to_u32(const void* p) {
    u32 a;
    asm("{ .reg .u64 t; cvta.to.shared.u64 t, %1; cvt.u32.u64 %0, t; }"
        : "=r"(a) : "l"(p));
    return a;
}
// 64B-stride swizzle: row r, 16B-chunk c (0..3)
__device__ __forceinline__ u32 swz(int r, int c) {
    return (u32)(r * 64 + (((c ^ ((r >> 1) & 3)) & 3) << 4));
}
__device__ __forceinline__ void ldsm_x4(u32& r0, u32& r1, u32& r2, u32& r3, u32 a) {
    asm volatile("ldmatrix.sync.aligned.m8n8.x4.shared.b16 {%0,%1,%2,%3}, [%4];"
                 : "=r"(r0), "=r"(r1), "=r"(r2), "=r"(r3) : "r"(a));
}
__device__ __forceinline__ void mma_bf16(float* c, const u32* a, const u32* b) {
    asm volatile(
        "mma.sync.aligned.m16n8k16.row.col.f32.bf16.bf16.f32 "
        "{%0,%1,%2,%3},{%4,%5,%6,%7},{%8,%9},{%0,%1,%2,%3};"
        : "+f"(c[0]), "+f"(c[1]), "+f"(c[2]), "+f"(c[3])
        : "r"(a[0]), "r"(a[1]), "r"(a[2]), "r"(a[3]), "r"(b[0]), "r"(b[1]));
}
__device__ __forceinline__ void cp16(u32 dst, const void* src) {
    asm volatile("cp.async.cg.shared.global [%0], [%1], 16;"
                 :: "r"(dst), "l"(src));
}
#define CP_COMMIT() asm volatile("cp.async.commit_group;" ::: "memory")
#define CP_WAIT0()  asm volatile("cp.async.wait_group 0;"  ::: "memory")
#define CP_WAIT1()  asm volatile("cp.async.wait_group 1;"  ::: "memory")

// split 8 floats -> bf16x8 hi + bf16x8 lo (error-compensated)
__device__ __forceinline__ void split8(const float* v, uint4& uh, uint4& ul) {
    u32 h[4], l[4];
#pragma unroll
    for (int q = 0; q < 4; q++) {
        float2 p = make_float2(v[2 * q], v[2 * q + 1]);
        __nv_bfloat162 hh = __float22bfloat162_rn(p);
        float2 hf = __bfloat1622float2(hh);
        __nv_bfloat162 ll = __float22bfloat162_rn(
            make_float2(p.x - hf.x, p.y - hf.y));
        h[q] = *(u32*)&hh;
        l[q] = *(u32*)&ll;
    }
    uh = make_uint4(h[0], h[1], h[2], h[3]);
    ul = make_uint4(l[0], l[1], l[2], l[3]);
}

// ---------------- weight prepack: transpose + hi/lo split + zero pad -------
__global__ void pack_w_kernel(const float* __restrict__ W, int sel)
{
    int KPAD = (sel == 0) ? KPAD_I : (sel == 1) ? KPAD_H : KPAD_O;
    __nv_bfloat16* imgHi = (sel == 0) ? g_Bi[0] : (sel == 1) ? g_Bh[0] : g_Bo[0];
    __nv_bfloat16* imgLo = (sel == 0) ? g_Bi[1] : (sel == 1) ? g_Bh[1] : g_Bo[1];
    int t = blockIdx.x * blockDim.x + threadIdx.x;
    if (t >= 256 * KPAD) return;
    int n = t / KPAD, kk = t % KPAD;
    int srck;
    if (sel == 0)      srck = (kk < BF) ? kk : -1;
    else if (sel == 1) srck = kk;
    else               srck = (kk < 160) ? (kk < AF ? kk : -1) : (AF + (kk - 160));
    float w = (srck >= 0) ? W[(size_t)srck * HD + n] : 0.f;
    __nv_bfloat16 hi = __float2bfloat16(w);
    __nv_bfloat16 lo = __float2bfloat16(w - __bfloat162float(hi));
    imgHi[(size_t)n * KPAD + kk] = hi;
    imgLo[(size_t)n * KPAD + kk] = lo;
}

// ---------------- A-operand prep kernels ------------------------------------
__global__ void __launch_bounds__(256) prep_bonds_kernel(const float* __restrict__ fB)
{
    long long t = (long long)blockIdx.x * blockDim.x + threadIdx.x;
    if (t >= (long long)NB * 20) return;
    int row = (int)(t / 20), cg = (int)(t % 20);
    int k0 = cg * 8;
    float v[8];
#pragma unroll
    for (int j = 0; j < 8; j++) {
        int k = k0 + j;
        v[j] = (k < BF) ? __ldg(fB + (size_t)row * BF + k) : 0.f;
    }
    uint4 uh, ul;
    split8(v, uh, ul);
    *(uint4*)(g_Ai[0] + (size_t)row * KPAD_I + k0) = uh;
    *(uint4*)(g_Ai[1] + (size_t)row * KPAD_I + k0) = ul;
}

__global__ void __launch_bounds__(256) prep_diff_kernel(
    int src, const int* __restrict__ b2a, const int* __restrict__ b2revb)
{
    const float* __restrict__ msg = (src == 0) ? g_msgA : g_msgB;
    long long t = (long long)blockIdx.x * blockDim.x + threadIdx.x;
    if (t >= (long long)NB * 32) return;
    int row = (int)(t >> 5), cg = (int)(t & 31);
    int k0 = cg * 8;
    const float* pa = g_amsg + (size_t)__ldg(b2a + row)    * HD + k0;
    const float* pm = msg    + (size_t)__ldg(b2revb + row) * HD + k0;
    float4 a0 = *(const float4*)(pa);
    float4 a1 = *(const float4*)(pa + 4);
    float4 m0 = *(const float4*)(pm);
    float4 m1 = *(const float4*)(pm + 4);
    float v[8] = { a0.x - m0.x, a0.y - m0.y, a0.z - m0.z, a0.w - m0.w,
                   a1.x - m1.x, a1.y - m1.y, a1.z - m1.z, a1.w - m1.w };
    uint4 uh, ul;
    split8(v, uh, ul);
    *(uint4*)(g_Ah[0] + (size_t)row * KPAD_H + k0) = uh;
    *(uint4*)(g_Ah[1] + (size_t)row * KPAD_H + k0) = ul;
}

__global__ void __launch_bounds__(256) prep_concat_kernel(const float* __restrict__ fA)
{
    long long t = (long long)blockIdx.x * blockDim.x + threadIdx.x;
    if (t >= (long long)NA * 52) return;
    int row = (int)(t / 52), cg = (int)(t % 52);
    int k0 = cg * 8;
    float v[8];
    if (cg < 20) {
#pragma unroll
        for (int j = 0; j < 8; j++) {
            int k = k0 + j;
            v[j] = (k < AF) ? __ldg(fA + (size_t)row * AF + k) : 0.f;
        }
    } else {
        const float* p = g_amsg + (size_t)row * HD + (k0 - 160);
        float4 a0 = *(const float4*)(p);
        float4 a1 = *(const float4*)(p + 4);
        v[0] = a0.x; v[1] = a0.y; v[2] = a0.z; v[3] = a0.w;
        v[4] = a1.x; v[5] = a1.y; v[6] = a1.z; v[7] = a1.w;
    }
    uint4 uh, ul;
    split8(v, uh, ul);
    *(uint4*)(g_Ao[0] + (size_t)row * KPAD_O + k0) = uh;
    *(uint4*)(g_Ao[1] + (size_t)row * KPAD_O + k0) = ul;
}

// ---------------- pure bf16 mma.sync GEMM, CTA 128x256, 3-stage pipeline ----
// MODE 0: g_inp = Ai @ Bi ; g_msgA = relu(g_inp)
// MODE 1: msgOut = relu(g_inp + Ah @ Bh)
// MODE 2: g_hid = relu(Ao @ Bo + b_o)
template <int MODE>
__global__ void __launch_bounds__(512, 1) mma_gemm_kernel(
    const float* __restrict__ bo, int srcSel)
{
    constexpr int NCH   = (MODE == 0) ? 5 : (MODE == 1) ? 8 : 13;
    constexpr int KPAD  = (MODE == 0) ? KPAD_I : (MODE == 1) ? KPAD_H : KPAD_O;
    constexpr int Mrows = (MODE == 2) ? NA : NB;

    float* __restrict__ msgOut = (srcSel == 0) ? g_msgB : g_msgA;
    const __nv_bfloat16* imgAH =
        (MODE == 0) ? g_Ai[0] : (MODE == 1) ? g_Ah[0] : g_Ao[0];
    const __nv_bfloat16* imgAL =
        (MODE == 0) ? g_Ai[1] : (MODE == 1) ? g_Ah[1] : g_Ao[1];
    const __nv_bfloat16* imgBH =
        (MODE == 0) ? g_Bi[0] : (MODE == 1) ? g_Bh[0] : g_Bo[0];
    const __nv_bfloat16* imgBL =
        (MODE == 0) ? g_Bi[1] : (MODE == 1) ? g_Bh[1] : g_Bo[1];

    extern __shared__ char smem[];
    const u32 sbase = smem_to_u32(smem);

    const int tid  = threadIdx.x;
    const int lane = tid & 31;
    const int wid  = tid >> 5;        // 0..15
    const int wm   = wid >> 2;        // 0..3 (M: 32 rows each)
    const int wn   = wid & 3;         // 0..3 (N: 64 cols each)
    const int bm   = blockIdx.x * BMT;

    // loader coords: lrow = tid>>2 (0..127), seg = tid&3
    const int lrow = tid >> 2;
    const int seg  = tid & 3;
    const int ar   = (bm + lrow < Mrows) ? bm + lrow : Mrows - 1;  // clamp
    const __nv_bfloat16* sAH = imgAH + (size_t)ar * KPAD + seg * 8;
    const __nv_bfloat16* sAL = imgAL + (size_t)ar * KPAD + seg * 8;
    const __nv_bfloat16* sBH0 = imgBH + (size_t)lrow * KPAD + seg * 8;
    const __nv_bfloat16* sBH1 = imgBH + (size_t)(128 + lrow) * KPAD + seg * 8;
    const __nv_bfloat16* sBL0 = imgBL + (size_t)lrow * KPAD + seg * 8;
    const __nv_bfloat16* sBL1 = imgBL + (size_t)(128 + lrow) * KPAD + seg * 8;
    const u32 dA  = swz(lrow, seg);
    const u32 dB0 = swz(lrow, seg);
    const u32 dB1 = swz(128 + lrow, seg);

    // ldsm lane addressing
    const int alrow = lane & 15;
    const int ahi   = (lane >> 4) & 1;   // A k-half
    const int blrow = (lane & 7) + ((lane & 16) ? 8 : 0);
    const int bhi   = (lane >> 3) & 1;   // B k-half

    float acc[2][8][4];
#pragma unroll
    for (int i = 0; i < 2; i++)
#pragma unroll
        for (int j = 0; j < 8; j++)
#pragma unroll
            for (int q = 0; q < 4; q++) acc[i][j][q] = 0.f;

    auto issue = [&](int ch, u32 buf) {
        const int ko = ch * BK;
        cp16(buf + OFF_A_HI + dA,  sAH + ko);
        cp16(buf + OFF_A_LO + dA,  sAL + ko);
        cp16(buf + OFF_B_HI + dB0, sBH0 + ko);
        cp16(buf + OFF_B_HI + dB1, sBH1 + ko);
        cp16(buf + OFF_B_LO + dB0, sBL0 + ko);
        cp16(buf + OFF_B_LO + dB1, sBL1 + ko);
        CP_COMMIT();
    };

    // ---- prologue: 2 stages in flight ----
    issue(0, sbase + 0 * BUFSZ);
    if (NCH > 1) issue(1, sbase + 1 * BUFSZ);

    int stage = 0;
#pragma unroll 1
    for (int ch = 0; ch < NCH; ch++) {
        if (ch + 1 < NCH) { CP_WAIT1(); } else { CP_WAIT0(); }
        __syncthreads();

        const u32 bufC = sbase + stage * BUFSZ;

        if (ch + 2 < NCH) {
            int ns = stage + 2; if (ns >= NSTAGE) ns -= NSTAGE;
            issue(ch + 2, sbase + ns * BUFSZ);
        }

#pragma unroll
        for (int s = 0; s < 2; s++) {
            u32 ah[2][4], al[2][4];
#pragma unroll
            for (int mi = 0; mi < 2; mi++) {
                int r = wm * 32 + mi * 16 + alrow;
                u32 ra = swz(r, 2 * s + ahi);
                ldsm_x4(ah[mi][0], ah[mi][1], ah[mi][2], ah[mi][3],
                        bufC + OFF_A_HI + ra);
                ldsm_x4(al[mi][0], al[mi][1], al[mi][2], al[mi][3],
                        bufC + OFF_A_LO + ra);
            }
#pragma unroll
            for (int nh = 0; nh < 2; nh++) {
                const int n0 = wn * 64 + nh * 32;
                u32 bh[4][2], bl[4][2];
                u32 rb0 = swz(n0 + blrow,      2 * s + bhi);
                u32 rb1 = swz(n0 + 16 + blrow, 2 * s + bhi);
                ldsm_x4(bh[0][0], bh[0][1], bh[1][0], bh[1][1], bufC + OFF_B_HI + rb0);
                ldsm_x4(bh[2][0], bh[2][1], bh[3][0], bh[3][1], bufC + OFF_B_HI + rb1);
                ldsm_x4(bl[0][0], bl[0][1], bl[1][0], bl[1][1], bufC + OFF_B_LO + rb0);
                ldsm_x4(bl[2][0], bl[2][1], bl[3][0], bl[3][1], bufC + OFF_B_LO + rb1);
                // term-major: 8 independent MMAs between acc reuses
#pragma unroll
                for (int mi = 0; mi < 2; mi++)
#pragma unroll
                    for (int nt = 0; nt < 4; nt++)
                        mma_bf16(acc[mi][nh * 4 + nt], ah[mi], bh[nt]);
#pragma unroll
                for (int mi = 0; mi < 2; mi++)
#pragma unroll
                    for (int nt = 0; nt < 4; nt++)
                        mma_bf16(acc[mi][nh * 4 + nt], ah[mi], bl[nt]);
#pragma unroll
                for (int mi = 0; mi < 2; mi++)
#pragma unroll
                    for (int nt = 0; nt < 4; nt++)
                        mma_bf16(acc[mi][nh * 4 + nt], al[mi], bh[nt]);
            }
        }

        stage = stage + 1; if (stage >= NSTAGE) stage = 0;
    }

    // ---- epilogue (fused) ----
    const int lr = lane >> 2;
    const int lc = (lane & 3) * 2;
#pragma unroll
    for (int mi = 0; mi < 2; mi++) {
        int r0 = bm + wm * 32 + mi * 16 + lr;
#pragma unroll
        for (int nj = 0; nj < 8; nj++) {
            int cc = wn * 64 + nj * 8 + lc;
#pragma unroll
            for (int hh = 0; hh < 2; hh++) {
                int r = r0 + hh * 8;
                if (r >= Mrows) continue;
                float vx = acc[mi][nj][hh * 2 + 0];
                float vy = acc[mi][nj][hh * 2 + 1];
                size_t o = (size_t)r * HD + cc;
                if (MODE == 0) {
                    *(float2*)(g_inp + o)  = make_float2(vx, vy);
                    *(float2*)(g_msgA + o) = make_float2(fmaxf(vx, 0.f),
                                                         fmaxf(vy, 0.f));
                } else if (MODE == 1) {
                    float2 ip = *(const float2*)(g_inp + o);
                    *(float2*)(msgOut + o) = make_float2(fmaxf(ip.x + vx, 0.f),
                                                         fmaxf(ip.y + vy, 0.f));
                } else {
                    float2 bb = *(const float2*)(bo + cc);
                    *(float2*)(g_hid + o) = make_float2(fmaxf(vx + bb.x, 0.f),
                                                        fmaxf(vy + bb.y, 0.f));
                }
            }
        }
    }
}

// ============================================================================
// gather-sum: g_amsg[a] = sum_{j<6} msg[a2b[a][j]]
// ============================================================================
__global__ void __launch_bounds__(256) gather_sum_kernel(
    int src, const int* __restrict__ a2b)
{
    const float* __restrict__ msg = (src == 0) ? g_msgA : g_msgB;
    long long t = (long long)blockIdx.x * blockDim.x + threadIdx.x;
    if (t >= (long long)NA * (HD / 4)) return;
    int a = (int)(t >> 6);
    int c = (int)(t & 63);
    const int* nb = a2b + (size_t)a * MAXNB;
    float4 acc = make_float4(0.f, 0.f, 0.f, 0.f);
#pragma unroll
    for (int j = 0; j < MAXNB; j++) {
        int b = __ldg(nb + j);
        float4 v = ((const float4*)(msg + (size_t)b * HD))[c];
        acc.x += v.x; acc.y += v.y; acc.z += v.z; acc.w += v.w;
    }
    ((float4*)(g_amsg + (size_t)a * HD))[c] = acc;
}

// ============================================================================
// mol mean
// ============================================================================
__global__ void __launch_bounds__(256) mol_mean_kernel(float* __restrict__ out)
{
    int t = blockIdx.x * blockDim.x + threadIdx.x;
    if (t >= NMOL * HD) return;
    int m = t / HD, j = t % HD;
    const float* base = g_hid + (size_t)(1 + m * APM) * HD + j;
    float s = 0.f;
#pragma unroll
    for (int a = 0; a < APM; a++) s += base[(size_t)a * HD];
    out[t] = s * (1.f / APM);
}

// ============================================================================
extern "C" void kernel_launch(void* const* d_in, const int* in_sizes, int n_in,
                              void* d_out, int out_size)
{
    const float* f_atoms = (const float*)d_in[0];
    const float* f_bonds = (const float*)d_in[1];
    const int*   a2b     = (const int*)d_in[2];
    const int*   b2a     = (const int*)d_in[3];
    const int*   b2revb  = (const int*)d_in[4];
    const float* W_i     = (const float*)d_in[5];
    const float* W_h     = (const float*)d_in[6];
    const float* W_o     = (const float*)d_in[7];
    const float* b_o     = (const float*)d_in[8];
    float* out = (float*)d_out;

    cudaFuncSetAttribute(mma_gemm_kernel<0>,
                         cudaFuncAttributeMaxDynamicSharedMemorySize, SMEM_TOTAL);
    cudaFuncSetAttribute(mma_gemm_kernel<1>,
                         cudaFuncAttributeMaxDynamicSharedMemorySize, SMEM_TOTAL);
    cudaFuncSetAttribute(mma_gemm_kernel<2>,
                         cudaFuncAttributeMaxDynamicSharedMemorySize, SMEM_TOTAL);

    pack_w_kernel<<<(256 * KPAD_I + 255) / 256, 256>>>(W_i, 0);
    pack_w_kernel<<<(256 * KPAD_H + 255) / 256, 256>>>(W_h, 1);
    pack_w_kernel<<<(256 * KPAD_O + 255) / 256, 256>>>(W_o, 2);

    const int GB = (NB + BMT - 1) / BMT;   // 2032
    const int GA = (NA + BMT - 1) / BMT;   // 938

    long long gsT = (long long)NA * (HD / 4);
    int gsBlocks  = (int)((gsT + 255) / 256);
    int mmBlocks  = (NMOL * HD + 255) / 256;
    long long p0T = (long long)NB * 20;
    long long p1T = (long long)NB * 32;
    long long p2T = (long long)NA * 52;
    int p0B = (int)((p0T + 255) / 256);
    int p1B = (int)((p1T + 255) / 256);
    int p2B = (int)((p2T + 255) / 256);

    // layer 0
    prep_bonds_kernel<<<p0B, 256>>>(f_bonds);
    mma_gemm_kernel<0><<<GB, 512, SMEM_TOTAL>>>(b_o, 0);
    // depth iter 1: msgA -> msgB
    gather_sum_kernel<<<gsBlocks, 256>>>(0, a2b);
    prep_diff_kernel<<<p1B, 256>>>(0, b2a, b2revb);
    mma_gemm_kernel<1><<<GB, 512, SMEM_TOTAL>>>(b_o, 0);
    // depth iter 2: msgB -> msgA
    gather_sum_kernel<<<gsBlocks, 256>>>(1, a2b);
    prep_diff_kernel<<<p1B, 256>>>(1, b2a, b2revb);
    mma_gemm_kernel<1><<<GB, 512, SMEM_TOTAL>>>(b_o, 1);
    // final aggregation + readout
    gather_sum_kernel<<<gsBlocks, 256>>>(0, a2b);
    prep_concat_kernel<<<p2B, 256>>>(f_atoms);
    mma_gemm_kernel<2><<<GA, 512, SMEM_TOTAL>>>(b_o, 0);
    mol_mean_kernel<<<mmBlocks, 256>>>(out);
}

// round 11
// speedup vs baseline: 1.1342x; 1.1342x over previous
#include <cuda_runtime.h>
#include <cuda_bf16.h>
#include <cstdint>
#include <cstddef>

#define NA 120001
#define NB 260001
#define AF 133
#define BF 147
#define HD 256
#define MAXNB 6
#define NMOL 6000
#define APM 20

#define BMT 128           // M rows per CTA
#define BNT 128           // N cols per CTA (blockIdx.x selects half)
#define BK  32            // K elements per chunk

#define KPAD_I 160
#define KPAD_H 256
#define KPAD_O 416

// SMEM per stage: A_HI/A_LO/B_HI/B_LO, each 128 rows x 64B (swizzled)
#define OFF_A_HI 0
#define OFF_A_LO 8192
#define OFF_B_HI 16384
#define OFF_B_LO 24576
#define BUFSZ    32768
#define NSTAGE   3
#define SMEM_TOTAL (NSTAGE * BUFSZ)   // 98304 -> 2 CTAs/SM

typedef unsigned int u32;

// ---------------- scratch (device globals; no allocation allowed) ----------
__device__ float g_inp [(size_t)NB * HD];
__device__ float g_msgA[(size_t)NB * HD];
__device__ float g_msgB[(size_t)NB * HD];
__device__ float g_amsg[(size_t)NA * HD];
__device__ float g_hid [(size_t)NA * HD];

// prepacked bf16 hi/lo A-operand images
__device__ __nv_bfloat16 g_Ai[2][(size_t)NB * KPAD_I];  // f_bonds padded
__device__ __nv_bfloat16 g_Ah[2][(size_t)NB * KPAD_H];  // bond-message diff
__device__ __nv_bfloat16 g_Ao[2][(size_t)NA * KPAD_O];  // f_atoms | amsg

// prepacked transposed weights, bf16 hi/lo: [term][N=256][Kpad]
__device__ __nv_bfloat16 g_Bi[2][256 * KPAD_I];
__device__ __nv_bfloat16 g_Bh[2][256 * KPAD_H];
__device__ __nv_bfloat16 g_Bo[2][256 * KPAD_O];

// ---------------- helpers ---------------------------------------------------
__device__ __forceinline__ u32 smem_to_u32(const void* p) {
    u32 a;
    asm("{ .reg .u64 t; cvta.to.shared.u64 t, %1; cvt.u32.u64 %0, t; }"
        : "=r"(a) : "l"(p));
    return a;
}
// 64B-stride swizzle: row r, 16B-chunk c (0..3)
__device__ __forceinline__ u32 swz(int r, int c) {
    return (u32)(r * 64 + (((c ^ ((r >> 1) & 3)) & 3) << 4));
}
__device__ __forceinline__ void ldsm_x4(u32& r0, u32& r1, u32& r2, u32& r3, u32 a) {
    asm volatile("ldmatrix.sync.aligned.m8n8.x4.shared.b16 {%0,%1,%2,%3}, [%4];"
                 : "=r"(r0), "=r"(r1), "=r"(r2), "=r"(r3) : "r"(a));
}
__device__ __forceinline__ void mma_bf16(float* c, const u32* a, const u32* b) {
    asm volatile(
        "mma.sync.aligned.m16n8k16.row.col.f32.bf16.bf16.f32 "
        "{%0,%1,%2,%3},{%4,%5,%6,%7},{%8,%9},{%0,%1,%2,%3};"
        : "+f"(c[0]), "+f"(c[1]), "+f"(c[2]), "+f"(c[3])
        : "r"(a[0]), "r"(a[1]), "r"(a[2]), "r"(a[3]), "r"(b[0]), "r"(b[1]));
}
__device__ __forceinline__ void cp16(u32 dst, const void* src) {
    asm volatile("cp.async.cg.shared.global [%0], [%1], 16;"
                 :: "r"(dst), "l"(src));
}
#define CP_COMMIT() asm volatile("cp.async.commit_group;" ::: "memory")
#define CP_WAIT0()  asm volatile("cp.async.wait_group 0;"  ::: "memory")
#define CP_WAIT1()  asm volatile("cp.async.wait_group 1;"  ::: "memory")

// split 8 floats -> bf16x8 hi + bf16x8 lo (error-compensated)
__device__ __forceinline__ void split8(const float* v, uint4& uh, uint4& ul) {
    u32 h[4], l[4];
#pragma unroll
    for (int q = 0; q < 4; q++) {
        float2 p = make_float2(v[2 * q], v[2 * q + 1]);
        __nv_bfloat162 hh = __float22bfloat162_rn(p);
        float2 hf = __bfloat1622float2(hh);
        __nv_bfloat162 ll = __float22bfloat162_rn(
            make_float2(p.x - hf.x, p.y - hf.y));
        h[q] = *(u32*)&hh;
        l[q] = *(u32*)&ll;
    }
    uh = make_uint4(h[0], h[1], h[2], h[3]);
    ul = make_uint4(l[0], l[1], l[2], l[3]);
}

// ---------------- weight prepack: transpose + hi/lo split + zero pad -------
__global__ void pack_w_kernel(const float* __restrict__ W, int sel)
{
    int KPAD = (sel == 0) ? KPAD_I : (sel == 1) ? KPAD_H : KPAD_O;
    __nv_bfloat16* imgHi = (sel == 0) ? g_Bi[0] : (sel == 1) ? g_Bh[0] : g_Bo[0];
    __nv_bfloat16* imgLo = (sel == 0) ? g_Bi[1] : (sel == 1) ? g_Bh[1] : g_Bo[1];
    int t = blockIdx.x * blockDim.x + threadIdx.x;
    if (t >= 256 * KPAD) return;
    int n = t / KPAD, kk = t % KPAD;
    int srck;
    if (sel == 0)      srck = (kk < BF) ? kk : -1;
    else if (sel == 1) srck = kk;
    else               srck = (kk < 160) ? (kk < AF ? kk : -1) : (AF + (kk - 160));
    float w = (srck >= 0) ? W[(size_t)srck * HD + n] : 0.f;
    __nv_bfloat16 hi = __float2bfloat16(w);
    __nv_bfloat16 lo = __float2bfloat16(w - __bfloat162float(hi));
    imgHi[(size_t)n * KPAD + kk] = hi;
    imgLo[(size_t)n * KPAD + kk] = lo;
}

// ---------------- A-operand prep kernels ------------------------------------
__global__ void __launch_bounds__(256) prep_bonds_kernel(const float* __restrict__ fB)
{
    long long t = (long long)blockIdx.x * blockDim.x + threadIdx.x;
    if (t >= (long long)NB * 20) return;
    int row = (int)(t / 20), cg = (int)(t % 20);
    int k0 = cg * 8;
    float v[8];
#pragma unroll
    for (int j = 0; j < 8; j++) {
        int k = k0 + j;
        v[j] = (k < BF) ? __ldg(fB + (size_t)row * BF + k) : 0.f;
    }
    uint4 uh, ul;
    split8(v, uh, ul);
    *(uint4*)(g_Ai[0] + (size_t)row * KPAD_I + k0) = uh;
    *(uint4*)(g_Ai[1] + (size_t)row * KPAD_I + k0) = ul;
}

__global__ void __launch_bounds__(256) prep_diff_kernel(
    int src, const int* __restrict__ b2a, const int* __restrict__ b2revb)
{
    const float* __restrict__ msg = (src == 0) ? g_msgA : g_msgB;
    long long t = (long long)blockIdx.x * blockDim.x + threadIdx.x;
    if (t >= (long long)NB * 32) return;
    int row = (int)(t >> 5), cg = (int)(t & 31);
    int k0 = cg * 8;
    const float* pa = g_amsg + (size_t)__ldg(b2a + row)    * HD + k0;
    const float* pm = msg    + (size_t)__ldg(b2revb + row) * HD + k0;
    float4 a0 = *(const float4*)(pa);
    float4 a1 = *(const float4*)(pa + 4);
    float4 m0 = *(const float4*)(pm);
    float4 m1 = *(const float4*)(pm + 4);
    float v[8] = { a0.x - m0.x, a0.y - m0.y, a0.z - m0.z, a0.w - m0.w,
                   a1.x - m1.x, a1.y - m1.y, a1.z - m1.z, a1.w - m1.w };
    uint4 uh, ul;
    split8(v, uh, ul);
    *(uint4*)(g_Ah[0] + (size_t)row * KPAD_H + k0) = uh;
    *(uint4*)(g_Ah[1] + (size_t)row * KPAD_H + k0) = ul;
}

__global__ void __launch_bounds__(256) prep_concat_kernel(const float* __restrict__ fA)
{
    long long t = (long long)blockIdx.x * blockDim.x + threadIdx.x;
    if (t >= (long long)NA * 52) return;
    int row = (int)(t / 52), cg = (int)(t % 52);
    int k0 = cg * 8;
    float v[8];
    if (cg < 20) {
#pragma unroll
        for (int j = 0; j < 8; j++) {
            int k = k0 + j;
            v[j] = (k < AF) ? __ldg(fA + (size_t)row * AF + k) : 0.f;
        }
    } else {
        const float* p = g_amsg + (size_t)row * HD + (k0 - 160);
        float4 a0 = *(const float4*)(p);
        float4 a1 = *(const float4*)(p + 4);
        v[0] = a0.x; v[1] = a0.y; v[2] = a0.z; v[3] = a0.w;
        v[4] = a1.x; v[5] = a1.y; v[6] = a1.z; v[7] = a1.w;
    }
    uint4 uh, ul;
    split8(v, uh, ul);
    *(uint4*)(g_Ao[0] + (size_t)row * KPAD_O + k0) = uh;
    *(uint4*)(g_Ao[1] + (size_t)row * KPAD_O + k0) = ul;
}

// ---------------- pure bf16 mma.sync GEMM, 3-stage cp.async pipeline --------
// Grid = (2, M-tiles): x = N-half, so the two N-halves of one M-tile are
// consecutive CTA ids -> co-scheduled -> second A read hits L2.
// MODE 0: g_inp = Ai @ Bi ; g_msgA = relu(g_inp)
// MODE 1: msgOut = relu(g_inp + Ah @ Bh)
// MODE 2: g_hid = relu(Ao @ Bo + b_o)
template <int MODE>
__global__ void __launch_bounds__(256, 2) mma_gemm_kernel(
    const float* __restrict__ bo, int srcSel)
{
    constexpr int NCH   = (MODE == 0) ? 5 : (MODE == 1) ? 8 : 13;
    constexpr int KPAD  = (MODE == 0) ? KPAD_I : (MODE == 1) ? KPAD_H : KPAD_O;
    constexpr int Mrows = (MODE == 2) ? NA : NB;

    float* __restrict__ msgOut = (srcSel == 0) ? g_msgB : g_msgA;
    const __nv_bfloat16* imgAH =
        (MODE == 0) ? g_Ai[0] : (MODE == 1) ? g_Ah[0] : g_Ao[0];
    const __nv_bfloat16* imgAL =
        (MODE == 0) ? g_Ai[1] : (MODE == 1) ? g_Ah[1] : g_Ao[1];
    const __nv_bfloat16* imgBH =
        (MODE == 0) ? g_Bi[0] : (MODE == 1) ? g_Bh[0] : g_Bo[0];
    const __nv_bfloat16* imgBL =
        (MODE == 0) ? g_Bi[1] : (MODE == 1) ? g_Bh[1] : g_Bo[1];

    extern __shared__ char smem[];
    const u32 sbase = smem_to_u32(smem);

    const int tid  = threadIdx.x;
    const int lane = tid & 31;
    const int wid  = tid >> 5;
    const int wm   = wid >> 1;        // 0..3
    const int wn   = wid & 1;         // 0..1
    const int bm   = blockIdx.y * BMT;   // M tile (slow axis)
    const int bn   = blockIdx.x * BNT;   // N half (fast axis -> paired ids)

    // loader rows: thread owns rows lrow0, lrow1 = 64+lrow0, 16B segment seg
    const int lrow0 = tid >> 2;
    const int lrow1 = 64 + lrow0;
    const int seg   = tid & 3;
    const int ar0 = (bm + lrow0 < Mrows) ? bm + lrow0 : Mrows - 1;
    const int ar1 = (bm + lrow1 < Mrows) ? bm + lrow1 : Mrows - 1;
    const __nv_bfloat16* sAH0 = imgAH + (size_t)ar0 * KPAD + seg * 8;
    const __nv_bfloat16* sAH1 = imgAH + (size_t)ar1 * KPAD + seg * 8;
    const __nv_bfloat16* sAL0 = imgAL + (size_t)ar0 * KPAD + seg * 8;
    const __nv_bfloat16* sAL1 = imgAL + (size_t)ar1 * KPAD + seg * 8;
    const __nv_bfloat16* sBH0 = imgBH + (size_t)(bn + lrow0) * KPAD + seg * 8;
    const __nv_bfloat16* sBH1 = imgBH + (size_t)(bn + lrow1) * KPAD + seg * 8;
    const __nv_bfloat16* sBL0 = imgBL + (size_t)(bn + lrow0) * KPAD + seg * 8;
    const __nv_bfloat16* sBL1 = imgBL + (size_t)(bn + lrow1) * KPAD + seg * 8;
    const u32 d0 = swz(lrow0, seg);
    const u32 d1 = swz(lrow1, seg);

    // ldsm lane addressing
    const int alrow = lane & 15;
    const int ahi   = (lane >> 4) & 1;   // A k-half
    const int blrow = (lane & 7) + ((lane & 16) ? 8 : 0);
    const int bhi   = (lane >> 3) & 1;   // B k-half

    float acc[2][8][4];
#pragma unroll
    for (int i = 0; i < 2; i++)
#pragma unroll
        for (int j = 0; j < 8; j++)
#pragma unroll
            for (int q = 0; q < 4; q++) acc[i][j][q] = 0.f;

    auto issue = [&](int ch, u32 buf) {
        const int ko = ch * BK;
        cp16(buf + OFF_A_HI + d0, sAH0 + ko);
        cp16(buf + OFF_A_HI + d1, sAH1 + ko);
        cp16(buf + OFF_A_LO + d0, sAL0 + ko);
        cp16(buf + OFF_A_LO + d1, sAL1 + ko);
        cp16(buf + OFF_B_HI + d0, sBH0 + ko);
        cp16(buf + OFF_B_HI + d1, sBH1 + ko);
        cp16(buf + OFF_B_LO + d0, sBL0 + ko);
        cp16(buf + OFF_B_LO + d1, sBL1 + ko);
        CP_COMMIT();
    };

    // ---- prologue: 2 stages in flight ----
    issue(0, sbase + 0 * BUFSZ);
    if (NCH > 1) issue(1, sbase + 1 * BUFSZ);

    int stage = 0;
#pragma unroll 1
    for (int ch = 0; ch < NCH; ch++) {
        // group ch must be complete; group ch+1 may remain in flight
        if (ch + 1 < NCH) { CP_WAIT1(); } else { CP_WAIT0(); }
        __syncthreads();

        const u32 bufC = sbase + stage * BUFSZ;

        // prefetch chunk ch+2 into the stage freed by chunk ch-1
        if (ch + 2 < NCH) {
            int ns = stage + 2; if (ns >= NSTAGE) ns -= NSTAGE;
            issue(ch + 2, sbase + ns * BUFSZ);
        }

#pragma unroll
        for (int s = 0; s < 2; s++) {
            u32 ah[2][4], al[2][4];
#pragma unroll
            for (int mi = 0; mi < 2; mi++) {
                int r = wm * 32 + mi * 16 + alrow;
                u32 ra = swz(r, 2 * s + ahi);
                ldsm_x4(ah[mi][0], ah[mi][1], ah[mi][2], ah[mi][3],
                        bufC + OFF_A_HI + ra);
                ldsm_x4(al[mi][0], al[mi][1], al[mi][2], al[mi][3],
                        bufC + OFF_A_LO + ra);
            }
#pragma unroll
            for (int nh = 0; nh < 2; nh++) {
                const int n0 = wn * 64 + nh * 32;
                u32 bh[4][2], bl[4][2];
                u32 rb0 = swz(n0 + blrow,      2 * s + bhi);
                u32 rb1 = swz(n0 + 16 + blrow, 2 * s + bhi);
                ldsm_x4(bh[0][0], bh[0][1], bh[1][0], bh[1][1], bufC + OFF_B_HI + rb0);
                ldsm_x4(bh[2][0], bh[2][1], bh[3][0], bh[3][1], bufC + OFF_B_HI + rb1);
                ldsm_x4(bl[0][0], bl[0][1], bl[1][0], bl[1][1], bufC + OFF_B_LO + rb0);
                ldsm_x4(bl[2][0], bl[2][1], bl[3][0], bl[3][1], bufC + OFF_B_LO + rb1);
                // term-major: 8 independent MMAs between acc reuses
#pragma unroll
                for (int mi = 0; mi < 2; mi++)
#pragma unroll
                    for (int nt = 0; nt < 4; nt++)
                        mma_bf16(acc[mi][nh * 4 + nt], ah[mi], bh[nt]);
#pragma unroll
                for (int mi = 0; mi < 2; mi++)
#pragma unroll
                    for (int nt = 0; nt < 4; nt++)
                        mma_bf16(acc[mi][nh * 4 + nt], ah[mi], bl[nt]);
#pragma unroll
                for (int mi = 0; mi < 2; mi++)
#pragma unroll
                    for (int nt = 0; nt < 4; nt++)
                        mma_bf16(acc[mi][nh * 4 + nt], al[mi], bh[nt]);
            }
        }

        stage = stage + 1; if (stage >= NSTAGE) stage = 0;
    }

    // ---- epilogue (fused) ----
    const int lr = lane >> 2;
    const int lc = (lane & 3) * 2;
#pragma unroll
    for (int mi = 0; mi < 2; mi++) {
        int r0 = bm + wm * 32 + mi * 16 + lr;
#pragma unroll
        for (int nj = 0; nj < 8; nj++) {
            int cc = bn + wn * 64 + nj * 8 + lc;
#pragma unroll
            for (int hh = 0; hh < 2; hh++) {
                int r = r0 + hh * 8;
                if (r >= Mrows) continue;
                float vx = acc[mi][nj][hh * 2 + 0];
                float vy = acc[mi][nj][hh * 2 + 1];
                size_t o = (size_t)r * HD + cc;
                if (MODE == 0) {
                    *(float2*)(g_inp + o)  = make_float2(vx, vy);
                    *(float2*)(g_msgA + o) = make_float2(fmaxf(vx, 0.f),
                                                         fmaxf(vy, 0.f));
                } else if (MODE == 1) {
                    float2 ip = *(const float2*)(g_inp + o);
                    *(float2*)(msgOut + o) = make_float2(fmaxf(ip.x + vx, 0.f),
                                                         fmaxf(ip.y + vy, 0.f));
                } else {
                    float2 bb = *(const float2*)(bo + cc);
                    *(float2*)(g_hid + o) = make_float2(fmaxf(vx + bb.x, 0.f),
                                                        fmaxf(vy + bb.y, 0.f));
                }
            }
        }
    }
}

// ============================================================================
// gather-sum: g_amsg[a] = sum_{j<6} msg[a2b[a][j]]
// ============================================================================
__global__ void __launch_bounds__(256) gather_sum_kernel(
    int src, const int* __restrict__ a2b)
{
    const float* __restrict__ msg = (src == 0) ? g_msgA : g_msgB;
    long long t = (long long)blockIdx.x * blockDim.x + threadIdx.x;
    if (t >= (long long)NA * (HD / 4)) return;
    int a = (int)(t >> 6);
    int c = (int)(t & 63);
    const int* nb = a2b + (size_t)a * MAXNB;
    float4 acc = make_float4(0.f, 0.f, 0.f, 0.f);
#pragma unroll
    for (int j = 0; j < MAXNB; j++) {
        int b = __ldg(nb + j);
        float4 v = ((const float4*)(msg + (size_t)b * HD))[c];
        acc.x += v.x; acc.y += v.y; acc.z += v.z; acc.w += v.w;
    }
    ((float4*)(g_amsg + (size_t)a * HD))[c] = acc;
}

// ============================================================================
// mol mean
// ============================================================================
__global__ void __launch_bounds__(256) mol_mean_kernel(float* __restrict__ out)
{
    int t = blockIdx.x * blockDim.x + threadIdx.x;
    if (t >= NMOL * HD) return;
    int m = t / HD, j = t % HD;
    const float* base = g_hid + (size_t)(1 + m * APM) * HD + j;
    float s = 0.f;
#pragma unroll
    for (int a = 0; a < APM; a++) s += base[(size_t)a * HD];
    out[t] = s * (1.f / APM);
}

// ============================================================================
extern "C" void kernel_launch(void* const* d_in, const int* in_sizes, int n_in,
                              void* d_out, int out_size)
{
    const float* f_atoms = (const float*)d_in[0];
    const float* f_bonds = (const float*)d_in[1];
    const int*   a2b     = (const int*)d_in[2];
    const int*   b2a     = (const int*)d_in[3];
    const int*   b2revb  = (const int*)d_in[4];
    const float* W_i     = (const float*)d_in[5];
    const float* W_h     = (const float*)d_in[6];
    const float* W_o     = (const float*)d_in[7];
    const float* b_o     = (const float*)d_in[8];
    float* out = (float*)d_out;

    cudaFuncSetAttribute(mma_gemm_kernel<0>,
                         cudaFuncAttributeMaxDynamicSharedMemorySize, SMEM_TOTAL);
    cudaFuncSetAttribute(mma_gemm_kernel<1>,
                         cudaFuncAttributeMaxDynamicSharedMemorySize, SMEM_TOTAL);
    cudaFuncSetAttribute(mma_gemm_kernel<2>,
                         cudaFuncAttributeMaxDynamicSharedMemorySize, SMEM_TOTAL);

    pack_w_kernel<<<(256 * KPAD_I + 255) / 256, 256>>>(W_i, 0);
    pack_w_kernel<<<(256 * KPAD_H + 255) / 256, 256>>>(W_h, 1);
    pack_w_kernel<<<(256 * KPAD_O + 255) / 256, 256>>>(W_o, 2);

    // x = N-half (fast), y = M-tile (slow): N-half pairs are adjacent CTA ids
    const dim3 GB(2, (NB + BMT - 1) / BMT);   // 2 x 2032
    const dim3 GA(2, (NA + BMT - 1) / BMT);   // 2 x 938

    long long gsT = (long long)NA * (HD / 4);
    int gsBlocks  = (int)((gsT + 255) / 256);
    int mmBlocks  = (NMOL * HD + 255) / 256;
    long long p0T = (long long)NB * 20;
    long long p1T = (long long)NB * 32;
    long long p2T = (long long)NA * 52;
    int p0B = (int)((p0T + 255) / 256);
    int p1B = (int)((p1T + 255) / 256);
    int p2B = (int)((p2T + 255) / 256);

    // layer 0
    prep_bonds_kernel<<<p0B, 256>>>(f_bonds);
    mma_gemm_kernel<0><<<GB, 256, SMEM_TOTAL>>>(b_o, 0);
    // depth iter 1: msgA -> msgB
    gather_sum_kernel<<<gsBlocks, 256>>>(0, a2b);
    prep_diff_kernel<<<p1B, 256>>>(0, b2a, b2revb);
    mma_gemm_kernel<1><<<GB, 256, SMEM_TOTAL>>>(b_o, 0);
    // depth iter 2: msgB -> msgA
    gather_sum_kernel<<<gsBlocks, 256>>>(1, a2b);
    prep_diff_kernel<<<p1B, 256>>>(1, b2a, b2revb);
    mma_gemm_kernel<1><<<GB, 256, SMEM_TOTAL>>>(b_o, 1);
    // final aggregation + readout
    gather_sum_kernel<<<gsBlocks, 256>>>(0, a2b);
    prep_concat_kernel<<<p2B, 256>>>(f_atoms);
    mma_gemm_kernel<2><<<GA, 256, SMEM_TOTAL>>>(b_o, 0);
    mol_mean_kernel<<<mmBlocks, 256>>>(out);
}

// round 12
// speedup vs baseline: 1.1686x; 1.0303x over previous
#include <cuda_runtime.h>
#include <cuda_bf16.h>
#include <cstdint>
#include <cstddef>

#define NA 120001
#define NB 260001
#define AF 133
#define BF 147
#define HD 256
#define MAXNB 6
#define NMOL 6000
#define APM 20

#define BMT 128           // M rows per CTA
#define BNT 128           // N cols per CTA (blockIdx.x selects half)
#define BK  32            // K elements per chunk

#define KPAD_I 160
#define KPAD_H 256
#define KPAD_O 416

// SMEM per stage: A_HI/A_LO/B_HI/B_LO, each 128 rows x 64B (swizzled)
#define OFF_A_HI 0
#define OFF_A_LO 8192
#define OFF_B_HI 16384
#define OFF_B_LO 24576
#define BUFSZ    32768
#define NSTAGE   3
#define SMEM_TOTAL (NSTAGE * BUFSZ)   // 98304 -> 2 CTAs/SM

typedef unsigned int u32;

// ---------------- scratch (device globals; no allocation allowed) ----------
__device__ float g_inp [(size_t)NB * HD];   // pre-activation; msg0 = relu(inp)
__device__ float g_msgA[(size_t)NB * HD];
__device__ float g_msgB[(size_t)NB * HD];
__device__ float g_amsg[(size_t)NA * HD];
__device__ float g_hid [(size_t)NA * HD];

// prepacked bf16 hi/lo A-operand images
__device__ __nv_bfloat16 g_Ai[2][(size_t)NB * KPAD_I];  // f_bonds padded
__device__ __nv_bfloat16 g_Ah[2][(size_t)NB * KPAD_H];  // bond-message diff
__device__ __nv_bfloat16 g_Ao[2][(size_t)NA * KPAD_O];  // f_atoms | amsg

// prepacked transposed weights, bf16 hi/lo: [term][N=256][Kpad]
__device__ __nv_bfloat16 g_Bi[2][256 * KPAD_I];
__device__ __nv_bfloat16 g_Bh[2][256 * KPAD_H];
__device__ __nv_bfloat16 g_Bo[2][256 * KPAD_O];

// message-source selector: 0 = relu(g_inp) on the fly, 1 = g_msgA, 2 = g_msgB
__device__ __forceinline__ const float* msg_src(int sel) {
    return (sel == 0) ? g_inp : (sel == 1) ? g_msgA : g_msgB;
}

// ---------------- helpers ---------------------------------------------------
__device__ __forceinline__ u32 smem_to_u32(const void* p) {
    u32 a;
    asm("{ .reg .u64 t; cvta.to.shared.u64 t, %1; cvt.u32.u64 %0, t; }"
        : "=r"(a) : "l"(p));
    return a;
}
// 64B-stride swizzle: row r, 16B-chunk c (0..3)
__device__ __forceinline__ u32 swz(int r, int c) {
    return (u32)(r * 64 + (((c ^ ((r >> 1) & 3)) & 3) << 4));
}
__device__ __forceinline__ void ldsm_x4(u32& r0, u32& r1, u32& r2, u32& r3, u32 a) {
    asm volatile("ldmatrix.sync.aligned.m8n8.x4.shared.b16 {%0,%1,%2,%3}, [%4];"
                 : "=r"(r0), "=r"(r1), "=r"(r2), "=r"(r3) : "r"(a));
}
__device__ __forceinline__ void mma_bf16(float* c, const u32* a, const u32* b) {
    asm volatile(
        "mma.sync.aligned.m16n8k16.row.col.f32.bf16.bf16.f32 "
        "{%0,%1,%2,%3},{%4,%5,%6,%7},{%8,%9},{%0,%1,%2,%3};"
        : "+f"(c[0]), "+f"(c[1]), "+f"(c[2]), "+f"(c[3])
        : "r"(a[0]), "r"(a[1]), "r"(a[2]), "r"(a[3]), "r"(b[0]), "r"(b[1]));
}
__device__ __forceinline__ void cp16(u32 dst, const void* src) {
    asm volatile("cp.async.cg.shared.global [%0], [%1], 16;"
                 :: "r"(dst), "l"(src));
}
#define CP_COMMIT() asm volatile("cp.async.commit_group;" ::: "memory")
#define CP_WAIT0()  asm volatile("cp.async.wait_group 0;"  ::: "memory")
#define CP_WAIT1()  asm volatile("cp.async.wait_group 1;"  ::: "memory")

// split 8 floats -> bf16x8 hi + bf16x8 lo (error-compensated)
__device__ __forceinline__ void split8(const float* v, uint4& uh, uint4& ul) {
    u32 h[4], l[4];
#pragma unroll
    for (int q = 0; q < 4; q++) {
        float2 p = make_float2(v[2 * q], v[2 * q + 1]);
        __nv_bfloat162 hh = __float22bfloat162_rn(p);
        float2 hf = __bfloat1622float2(hh);
        __nv_bfloat162 ll = __float22bfloat162_rn(
            make_float2(p.x - hf.x, p.y - hf.y));
        h[q] = *(u32*)&hh;
        l[q] = *(u32*)&ll;
    }
    uh = make_uint4(h[0], h[1], h[2], h[3]);
    ul = make_uint4(l[0], l[1], l[2], l[3]);
}

// ---------------- weight prepack: transpose + hi/lo split + zero pad -------
__global__ void pack_w_kernel(const float* __restrict__ W, int sel)
{
    int KPAD = (sel == 0) ? KPAD_I : (sel == 1) ? KPAD_H : KPAD_O;
    __nv_bfloat16* imgHi = (sel == 0) ? g_Bi[0] : (sel == 1) ? g_Bh[0] : g_Bo[0];
    __nv_bfloat16* imgLo = (sel == 0) ? g_Bi[1] : (sel == 1) ? g_Bh[1] : g_Bo[1];
    int t = blockIdx.x * blockDim.x + threadIdx.x;
    if (t >= 256 * KPAD) return;
    int n = t / KPAD, kk = t % KPAD;
    int srck;
    if (sel == 0)      srck = (kk < BF) ? kk : -1;
    else if (sel == 1) srck = kk;
    else               srck = (kk < 160) ? (kk < AF ? kk : -1) : (AF + (kk - 160));
    float w = (srck >= 0) ? W[(size_t)srck * HD + n] : 0.f;
    __nv_bfloat16 hi = __float2bfloat16(w);
    __nv_bfloat16 lo = __float2bfloat16(w - __bfloat162float(hi));
    imgHi[(size_t)n * KPAD + kk] = hi;
    imgLo[(size_t)n * KPAD + kk] = lo;
}

// ---------------- A-operand prep kernels ------------------------------------
__global__ void __launch_bounds__(256) prep_bonds_kernel(const float* __restrict__ fB)
{
    long long t = (long long)blockIdx.x * blockDim.x + threadIdx.x;
    if (t >= (long long)NB * 20) return;
    int row = (int)(t / 20), cg = (int)(t % 20);
    int k0 = cg * 8;
    float v[8];
#pragma unroll
    for (int j = 0; j < 8; j++) {
        int k = k0 + j;
        v[j] = (k < BF) ? __ldg(fB + (size_t)row * BF + k) : 0.f;
    }
    uint4 uh, ul;
    split8(v, uh, ul);
    *(uint4*)(g_Ai[0] + (size_t)row * KPAD_I + k0) = uh;
    *(uint4*)(g_Ai[1] + (size_t)row * KPAD_I + k0) = ul;
}

// d[b] = amsg[b2a[b]] - msg[b2revb[b]] -> g_Ah hi/lo  (msg via selector)
__global__ void __launch_bounds__(256) prep_diff_kernel(
    int sel, const int* __restrict__ b2a, const int* __restrict__ b2revb)
{
    const float* __restrict__ msg = msg_src(sel);
    long long t = (long long)blockIdx.x * blockDim.x + threadIdx.x;
    if (t >= (long long)NB * 32) return;
    int row = (int)(t >> 5), cg = (int)(t & 31);
    int k0 = cg * 8;
    const float* pa = g_amsg + (size_t)__ldg(b2a + row)    * HD + k0;
    const float* pm = msg    + (size_t)__ldg(b2revb + row) * HD + k0;
    float4 a0 = *(const float4*)(pa);
    float4 a1 = *(const float4*)(pa + 4);
    float4 m0 = *(const float4*)(pm);
    float4 m1 = *(const float4*)(pm + 4);
    if (sel == 0) {   // message0 = relu(inp) computed on the fly
        m0.x = fmaxf(m0.x, 0.f); m0.y = fmaxf(m0.y, 0.f);
        m0.z = fmaxf(m0.z, 0.f); m0.w = fmaxf(m0.w, 0.f);
        m1.x = fmaxf(m1.x, 0.f); m1.y = fmaxf(m1.y, 0.f);
        m1.z = fmaxf(m1.z, 0.f); m1.w = fmaxf(m1.w, 0.f);
    }
    float v[8] = { a0.x - m0.x, a0.y - m0.y, a0.z - m0.z, a0.w - m0.w,
                   a1.x - m1.x, a1.y - m1.y, a1.z - m1.z, a1.w - m1.w };
    uint4 uh, ul;
    split8(v, uh, ul);
    *(uint4*)(g_Ah[0] + (size_t)row * KPAD_H + k0) = uh;
    *(uint4*)(g_Ah[1] + (size_t)row * KPAD_H + k0) = ul;
}

// fused: [f_atoms | gather-sum(g_msgA)] -> g_Ao hi/lo (no g_amsg round-trip)
__global__ void __launch_bounds__(256) prep_concat_gather_kernel(
    const float* __restrict__ fA, const int* __restrict__ a2b)
{
    long long t = (long long)blockIdx.x * blockDim.x + threadIdx.x;
    if (t >= (long long)NA * 52) return;
    int row = (int)(t / 52), cg = (int)(t % 52);
    int k0 = cg * 8;
    float v[8];
    if (cg < 20) {
#pragma unroll
        for (int j = 0; j < 8; j++) {
            int k = k0 + j;
            v[j] = (k < AF) ? __ldg(fA + (size_t)row * AF + k) : 0.f;
        }
    } else {
        int ko = k0 - 160;   // 0..248
        const int* nb = a2b + (size_t)row * MAXNB;
#pragma unroll
        for (int j = 0; j < 8; j++) v[j] = 0.f;
#pragma unroll
        for (int j = 0; j < MAXNB; j++) {
            int b = __ldg(nb + j);
            const float* p = g_msgA + (size_t)b * HD + ko;
            float4 a0 = *(const float4*)(p);
            float4 a1 = *(const float4*)(p + 4);
            v[0] += a0.x; v[1] += a0.y; v[2] += a0.z; v[3] += a0.w;
            v[4] += a1.x; v[5] += a1.y; v[6] += a1.z; v[7] += a1.w;
        }
    }
    uint4 uh, ul;
    split8(v, uh, ul);
    *(uint4*)(g_Ao[0] + (size_t)row * KPAD_O + k0) = uh;
    *(uint4*)(g_Ao[1] + (size_t)row * KPAD_O + k0) = ul;
}

// ---------------- pure bf16 mma.sync GEMM, 3-stage cp.async pipeline --------
// Grid = (2, M-tiles): N-half pairs are adjacent CTA ids (L2 A-reuse).
// MODE 0: g_inp = Ai @ Bi                       (message0 = relu(inp) implicit)
// MODE 1: msgOut = relu(g_inp + Ah @ Bh)
// MODE 2: g_hid = relu(Ao @ Bo + b_o)
template <int MODE>
__global__ void __launch_bounds__(256, 2) mma_gemm_kernel(
    const float* __restrict__ bo, int srcSel)
{
    constexpr int NCH   = (MODE == 0) ? 5 : (MODE == 1) ? 8 : 13;
    constexpr int KPAD  = (MODE == 0) ? KPAD_I : (MODE == 1) ? KPAD_H : KPAD_O;
    constexpr int Mrows = (MODE == 2) ? NA : NB;

    float* __restrict__ msgOut = (srcSel == 0) ? g_msgB : g_msgA;
    const __nv_bfloat16* imgAH =
        (MODE == 0) ? g_Ai[0] : (MODE == 1) ? g_Ah[0] : g_Ao[0];
    const __nv_bfloat16* imgAL =
        (MODE == 0) ? g_Ai[1] : (MODE == 1) ? g_Ah[1] : g_Ao[1];
    const __nv_bfloat16* imgBH =
        (MODE == 0) ? g_Bi[0] : (MODE == 1) ? g_Bh[0] : g_Bo[0];
    const __nv_bfloat16* imgBL =
        (MODE == 0) ? g_Bi[1] : (MODE == 1) ? g_Bh[1] : g_Bo[1];

    extern __shared__ char smem[];
    const u32 sbase = smem_to_u32(smem);

    const int tid  = threadIdx.x;
    const int lane = tid & 31;
    const int wid  = tid >> 5;
    const int wm   = wid >> 1;        // 0..3
    const int wn   = wid & 1;         // 0..1
    const int bm   = blockIdx.y * BMT;   // M tile (slow axis)
    const int bn   = blockIdx.x * BNT;   // N half (fast axis -> paired ids)

    // loader rows: thread owns rows lrow0, lrow1 = 64+lrow0, 16B segment seg
    const int lrow0 = tid >> 2;
    const int lrow1 = 64 + lrow0;
    const int seg   = tid & 3;
    const int ar0 = (bm + lrow0 < Mrows) ? bm + lrow0 : Mrows - 1;
    const int ar1 = (bm + lrow1 < Mrows) ? bm + lrow1 : Mrows - 1;
    const __nv_bfloat16* sAH0 = imgAH + (size_t)ar0 * KPAD + seg * 8;
    const __nv_bfloat16* sAH1 = imgAH + (size_t)ar1 * KPAD + seg * 8;
    const __nv_bfloat16* sAL0 = imgAL + (size_t)ar0 * KPAD + seg * 8;
    const __nv_bfloat16* sAL1 = imgAL + (size_t)ar1 * KPAD + seg * 8;
    const __nv_bfloat16* sBH0 = imgBH + (size_t)(bn + lrow0) * KPAD + seg * 8;
    const __nv_bfloat16* sBH1 = imgBH + (size_t)(bn + lrow1) * KPAD + seg * 8;
    const __nv_bfloat16* sBL0 = imgBL + (size_t)(bn + lrow0) * KPAD + seg * 8;
    const __nv_bfloat16* sBL1 = imgBL + (size_t)(bn + lrow1) * KPAD + seg * 8;
    const u32 d0 = swz(lrow0, seg);
    const u32 d1 = swz(lrow1, seg);

    // ldsm lane addressing
    const int alrow = lane & 15;
    const int ahi   = (lane >> 4) & 1;   // A k-half
    const int blrow = (lane & 7) + ((lane & 16) ? 8 : 0);
    const int bhi   = (lane >> 3) & 1;   // B k-half

    float acc[2][8][4];
#pragma unroll
    for (int i = 0; i < 2; i++)
#pragma unroll
        for (int j = 0; j < 8; j++)
#pragma unroll
            for (int q = 0; q < 4; q++) acc[i][j][q] = 0.f;

    auto issue = [&](int ch, u32 buf) {
        const int ko = ch * BK;
        cp16(buf + OFF_A_HI + d0, sAH0 + ko);
        cp16(buf + OFF_A_HI + d1, sAH1 + ko);
        cp16(buf + OFF_A_LO + d0, sAL0 + ko);
        cp16(buf + OFF_A_LO + d1, sAL1 + ko);
        cp16(buf + OFF_B_HI + d0, sBH0 + ko);
        cp16(buf + OFF_B_HI + d1, sBH1 + ko);
        cp16(buf + OFF_B_LO + d0, sBL0 + ko);
        cp16(buf + OFF_B_LO + d1, sBL1 + ko);
        CP_COMMIT();
    };

    // ---- prologue: 2 stages in flight ----
    issue(0, sbase + 0 * BUFSZ);
    if (NCH > 1) issue(1, sbase + 1 * BUFSZ);

    int stage = 0;
#pragma unroll 1
    for (int ch = 0; ch < NCH; ch++) {
        if (ch + 1 < NCH) { CP_WAIT1(); } else { CP_WAIT0(); }
        __syncthreads();

        const u32 bufC = sbase + stage * BUFSZ;

        if (ch + 2 < NCH) {
            int ns = stage + 2; if (ns >= NSTAGE) ns -= NSTAGE;
            issue(ch + 2, sbase + ns * BUFSZ);
        }

#pragma unroll
        for (int s = 0; s < 2; s++) {
            u32 ah[2][4], al[2][4];
#pragma unroll
            for (int mi = 0; mi < 2; mi++) {
                int r = wm * 32 + mi * 16 + alrow;
                u32 ra = swz(r, 2 * s + ahi);
                ldsm_x4(ah[mi][0], ah[mi][1], ah[mi][2], ah[mi][3],
                        bufC + OFF_A_HI + ra);
                ldsm_x4(al[mi][0], al[mi][1], al[mi][2], al[mi][3],
                        bufC + OFF_A_LO + ra);
            }
#pragma unroll
            for (int nh = 0; nh < 2; nh++) {
                const int n0 = wn * 64 + nh * 32;
                u32 bh[4][2], bl[4][2];
                u32 rb0 = swz(n0 + blrow,      2 * s + bhi);
                u32 rb1 = swz(n0 + 16 + blrow, 2 * s + bhi);
                ldsm_x4(bh[0][0], bh[0][1], bh[1][0], bh[1][1], bufC + OFF_B_HI + rb0);
                ldsm_x4(bh[2][0], bh[2][1], bh[3][0], bh[3][1], bufC + OFF_B_HI + rb1);
                ldsm_x4(bl[0][0], bl[0][1], bl[1][0], bl[1][1], bufC + OFF_B_LO + rb0);
                ldsm_x4(bl[2][0], bl[2][1], bl[3][0], bl[3][1], bufC + OFF_B_LO + rb1);
                // term-major: 8 independent MMAs between acc reuses
#pragma unroll
                for (int mi = 0; mi < 2; mi++)
#pragma unroll
                    for (int nt = 0; nt < 4; nt++)
                        mma_bf16(acc[mi][nh * 4 + nt], ah[mi], bh[nt]);
#pragma unroll
                for (int mi = 0; mi < 2; mi++)
#pragma unroll
                    for (int nt = 0; nt < 4; nt++)
                        mma_bf16(acc[mi][nh * 4 + nt], ah[mi], bl[nt]);
#pragma unroll
                for (int mi = 0; mi < 2; mi++)
#pragma unroll
                    for (int nt = 0; nt < 4; nt++)
                        mma_bf16(acc[mi][nh * 4 + nt], al[mi], bh[nt]);
            }
        }

        stage = stage + 1; if (stage >= NSTAGE) stage = 0;
    }

    // ---- epilogue (fused) ----
    const int lr = lane >> 2;
    const int lc = (lane & 3) * 2;
#pragma unroll
    for (int mi = 0; mi < 2; mi++) {
        int r0 = bm + wm * 32 + mi * 16 + lr;
#pragma unroll
        for (int nj = 0; nj < 8; nj++) {
            int cc = bn + wn * 64 + nj * 8 + lc;
#pragma unroll
            for (int hh = 0; hh < 2; hh++) {
                int r = r0 + hh * 8;
                if (r >= Mrows) continue;
                float vx = acc[mi][nj][hh * 2 + 0];
                float vy = acc[mi][nj][hh * 2 + 1];
                size_t o = (size_t)r * HD + cc;
                if (MODE == 0) {
                    // store pre-activation only; readers apply relu on the fly
                    *(float2*)(g_inp + o) = make_float2(vx, vy);
                } else if (MODE == 1) {
                    float2 ip = *(const float2*)(g_inp + o);
                    *(float2*)(msgOut + o) = make_float2(fmaxf(ip.x + vx, 0.f),
                                                         fmaxf(ip.y + vy, 0.f));
                } else {
                    float2 bb = *(const float2*)(bo + cc);
                    *(float2*)(g_hid + o) = make_float2(fmaxf(vx + bb.x, 0.f),
                                                        fmaxf(vy + bb.y, 0.f));
                }
            }
        }
    }
}

// ============================================================================
// gather-sum: g_amsg[a] = sum_{j<6} msg[a2b[a][j]]   (msg via selector)
// ============================================================================
__global__ void __launch_bounds__(256) gather_sum_kernel(
    int sel, const int* __restrict__ a2b)
{
    const float* __restrict__ msg = msg_src(sel);
    long long t = (long long)blockIdx.x * blockDim.x + threadIdx.x;
    if (t >= (long long)NA * (HD / 4)) return;
    int a = (int)(t >> 6);
    int c = (int)(t & 63);
    const int* nb = a2b + (size_t)a * MAXNB;
    float4 acc = make_float4(0.f, 0.f, 0.f, 0.f);
    if (sel == 0) {
#pragma unroll
        for (int j = 0; j < MAXNB; j++) {
            int b = __ldg(nb + j);
            float4 v = ((const float4*)(msg + (size_t)b * HD))[c];
            acc.x += fmaxf(v.x, 0.f); acc.y += fmaxf(v.y, 0.f);
            acc.z += fmaxf(v.z, 0.f); acc.w += fmaxf(v.w, 0.f);
        }
    } else {
#pragma unroll
        for (int j = 0; j < MAXNB; j++) {
            int b = __ldg(nb + j);
            float4 v = ((const float4*)(msg + (size_t)b * HD))[c];
            acc.x += v.x; acc.y += v.y; acc.z += v.z; acc.w += v.w;
        }
    }
    ((float4*)(g_amsg + (size_t)a * HD))[c] = acc;
}

// ============================================================================
// mol mean
// ============================================================================
__global__ void __launch_bounds__(256) mol_mean_kernel(float* __restrict__ out)
{
    int t = blockIdx.x * blockDim.x + threadIdx.x;
    if (t >= NMOL * HD) return;
    int m = t / HD, j = t % HD;
    const float* base = g_hid + (size_t)(1 + m * APM) * HD + j;
    float s = 0.f;
#pragma unroll
    for (int a = 0; a < APM; a++) s += base[(size_t)a * HD];
    out[t] = s * (1.f / APM);
}

// ============================================================================
extern "C" void kernel_launch(void* const* d_in, const int* in_sizes, int n_in,
                              void* d_out, int out_size)
{
    const float* f_atoms = (const float*)d_in[0];
    const float* f_bonds = (const float*)d_in[1];
    const int*   a2b     = (const int*)d_in[2];
    const int*   b2a     = (const int*)d_in[3];
    const int*   b2revb  = (const int*)d_in[4];
    const float* W_i     = (const float*)d_in[5];
    const float* W_h     = (const float*)d_in[6];
    const float* W_o     = (const float*)d_in[7];
    const float* b_o     = (const float*)d_in[8];
    float* out = (float*)d_out;

    cudaFuncSetAttribute(mma_gemm_kernel<0>,
                         cudaFuncAttributeMaxDynamicSharedMemorySize, SMEM_TOTAL);
    cudaFuncSetAttribute(mma_gemm_kernel<1>,
                         cudaFuncAttributeMaxDynamicSharedMemorySize, SMEM_TOTAL);
    cudaFuncSetAttribute(mma_gemm_kernel<2>,
                         cudaFuncAttributeMaxDynamicSharedMemorySize, SMEM_TOTAL);

    pack_w_kernel<<<(256 * KPAD_I + 255) / 256, 256>>>(W_i, 0);
    pack_w_kernel<<<(256 * KPAD_H + 255) / 256, 256>>>(W_h, 1);
    pack_w_kernel<<<(256 * KPAD_O + 255) / 256, 256>>>(W_o, 2);

    // x = N-half (fast), y = M-tile (slow): N-half pairs are adjacent CTA ids
    const dim3 GB(2, (NB + BMT - 1) / BMT);   // 2 x 2032
    const dim3 GA(2, (NA + BMT - 1) / BMT);   // 2 x 938

    long long gsT = (long long)NA * (HD / 4);
    int gsBlocks  = (int)((gsT + 255) / 256);
    int mmBlocks  = (NMOL * HD + 255) / 256;
    long long p0T = (long long)NB * 20;
    long long p1T = (long long)NB * 32;
    long long p2T = (long long)NA * 52;
    int p0B = (int)((p0T + 255) / 256);
    int p1B = (int)((p1T + 255) / 256);
    int p2B = (int)((p2T + 255) / 256);

    // layer 0 (message0 = relu(g_inp), never materialized)
    prep_bonds_kernel<<<p0B, 256>>>(f_bonds);
    mma_gemm_kernel<0><<<GB, 256, SMEM_TOTAL>>>(b_o, 0);
    // depth iter 1: relu(inp) -> msgB
    gather_sum_kernel<<<gsBlocks, 256>>>(0, a2b);
    prep_diff_kernel<<<p1B, 256>>>(0, b2a, b2revb);
    mma_gemm_kernel<1><<<GB, 256, SMEM_TOTAL>>>(b_o, 0);
    // depth iter 2: msgB -> msgA
    gather_sum_kernel<<<gsBlocks, 256>>>(2, a2b);
    prep_diff_kernel<<<p1B, 256>>>(2, b2a, b2revb);
    mma_gemm_kernel<1><<<GB, 256, SMEM_TOTAL>>>(b_o, 1);
    // final: fused gather + concat, then readout
    prep_concat_gather_kernel<<<p2B, 256>>>(f_atoms, a2b);
    mma_gemm_kernel<2><<<GA, 256, SMEM_TOTAL>>>(b_o, 0);
    mol_mean_kernel<<<mmBlocks, 256>>>(out);
}